// round 3
// baseline (speedup 1.0000x reference)
#include <cuda_runtime.h>
#include <math.h>

#define H 1024
#define L 512
#define V 50257

// ---------------- scratch (allocation-free; __device__ global) ----------------
#define OFF_VEC1   0        // [embedded(1024), h(1024)]
#define OFF_VEC2   2048     // [embedded(1024), attn_applied(1024)]
#define OFF_ALOG   4096     // attn logits (512)
#define OFF_AW     4608     // attn weights (512)
#define OFF_APART  5120     // 8 x 1024 partial sums for attn_applied
#define OFF_X      13312    // GRU input x (1024)
#define OFF_GI     14336    // gi (3072)
#define OFF_GH     17408    // gh (3072)
#define OFF_HNEW   20480    // h_new (1024)
#define OFF_LOGITS 21504    // vocab logits (50257)
#define OFF_PART   71808    // 240 partial sums for sum-exp
#define SCRATCH_FLOATS 72192

__device__ float g_scratch[SCRATCH_FLOATS];
__device__ int   g_maxbits;   // ordered-int encoding of running max logit

// monotone float<->int map (valid for all finite floats)
__device__ __forceinline__ int f2ord(float f) {
    int i = __float_as_int(f);
    return (i >= 0) ? i : (i ^ 0x7FFFFFFF);
}
__device__ __forceinline__ float ord2f(int o) {
    int b = (o >= 0) ? o : (o ^ 0x7FFFFFFF);
    return __int_as_float(b);
}

// ---------------- K1: gather embedding + hidden, reset max ----------------
__global__ void k_init(const int* __restrict__ idx,
                       const float* __restrict__ hidden,
                       const float* __restrict__ emb) {
    int t = blockIdx.x * blockDim.x + threadIdx.x;
    int row = idx[0];
    if (t < H) {
        float e = emb[(size_t)row * H + t];
        g_scratch[OFF_VEC1 + t] = e;
        g_scratch[OFF_VEC2 + t] = e;
    } else if (t < 2 * H) {
        g_scratch[OFF_VEC1 + t] = hidden[t - H];
    }
    if (t == 0) g_maxbits = 0x80000000; // INT_MIN
}

// ---------------- generic warp-per-row matvec: out[r] = W[r,:].v + b[r] ----------------
// v/out addressed as offsets into g_scratch (no host-side symbol lookup needed).
// mode 0: plain, 1: relu, 2: vocab logits (one atomicMax per block)
__global__ void __launch_bounds__(256)
k_matvec(const float* __restrict__ W,
         const float* __restrict__ b,
         int v_off, int out_off,
         int rows, int cols, int mode) {
    extern __shared__ float sv[];
    __shared__ float srow[8];
    const float* v = g_scratch + v_off;
    float* out = g_scratch + out_off;
    int n4 = cols >> 2;
    for (int i = threadIdx.x; i < n4; i += blockDim.x)
        ((float4*)sv)[i] = ((const float4*)v)[i];
    __syncthreads();

    int warp = threadIdx.x >> 5, lane = threadIdx.x & 31;
    int row = blockIdx.x * 8 + warp;
    float r = -INFINITY;
    if (row < rows) {
        const float4* wr = (const float4*)(W + (size_t)row * cols);
        const float4* v4 = (const float4*)sv;
        float acc = 0.f;
        for (int i = lane; i < n4; i += 32) {
            float4 w = wr[i];
            float4 x = v4[i];
            acc += w.x * x.x + w.y * x.y + w.z * x.z + w.w * x.w;
        }
        #pragma unroll
        for (int o = 16; o; o >>= 1) acc += __shfl_xor_sync(0xFFFFFFFFu, acc, o);
        if (lane == 0) {
            r = acc + b[row];
            if (mode == 1) r = fmaxf(r, 0.f);
            out[row] = r;
        }
    }
    if (mode == 2) {
        if (lane == 0) srow[warp] = r;
        __syncthreads();
        if (threadIdx.x == 0) {
            float m = srow[0];
            #pragma unroll
            for (int w = 1; w < 8; w++) m = fmaxf(m, srow[w]);
            atomicMax(&g_maxbits, f2ord(m));
        }
    }
}

// ---------------- K3: softmax over 512 attn logits ----------------
__global__ void k_attn_softmax(float* __restrict__ out_full) {
    __shared__ float sm[512];
    int t = threadIdx.x;
    float v = g_scratch[OFF_ALOG + t];
    sm[t] = v;
    __syncthreads();
    for (int s = 256; s > 0; s >>= 1) {
        if (t < s) sm[t] = fmaxf(sm[t], sm[t + s]);
        __syncthreads();
    }
    float mx = sm[0];
    __syncthreads();
    float e = expf(v - mx);
    sm[t] = e;
    __syncthreads();
    for (int s = 256; s > 0; s >>= 1) {
        if (t < s) sm[t] += sm[t + s];
        __syncthreads();
    }
    float aw = e / sm[0];
    g_scratch[OFF_AW + t] = aw;
    out_full[V + H + t] = aw;   // third output: attn_weights
}

// ---------------- K4a: attn_applied partial sums over L chunks ----------------
__global__ void k_attn_apply_part(const float* __restrict__ enc) {
    __shared__ float saw[64];
    int col = blockIdx.x * blockDim.x + threadIdx.x;   // 0..1023
    int lc = blockIdx.y;                               // 0..7
    if (threadIdx.x < 64) saw[threadIdx.x] = g_scratch[OFF_AW + lc * 64 + threadIdx.x];
    __syncthreads();
    float s = 0.f;
    int base = lc * 64;
    #pragma unroll 8
    for (int l = 0; l < 64; l++)
        s += saw[l] * enc[(size_t)(base + l) * H + col];
    g_scratch[OFF_APART + lc * H + col] = s;
}

// ---------------- K4b: reduce partials -> vec2[1024:2048] ----------------
__global__ void k_attn_apply_reduce() {
    int col = blockIdx.x * blockDim.x + threadIdx.x;
    float s = 0.f;
    #pragma unroll
    for (int p = 0; p < 8; p++) s += g_scratch[OFF_APART + p * H + col];
    g_scratch[OFF_VEC2 + H + col] = s;
}

// ---------------- K7: GRU gate math ----------------
__global__ void k_gates(float* __restrict__ out_full) {
    int j = blockIdx.x * blockDim.x + threadIdx.x;    // 0..1023
    float gir = g_scratch[OFF_GI + j],        ghr = g_scratch[OFF_GH + j];
    float giz = g_scratch[OFF_GI + H + j],    ghz = g_scratch[OFF_GH + H + j];
    float gin = g_scratch[OFF_GI + 2*H + j],  ghn = g_scratch[OFF_GH + 2*H + j];
    float r = 1.f / (1.f + expf(-(gir + ghr)));
    float z = 1.f / (1.f + expf(-(giz + ghz)));
    float n = tanhf(gin + r * ghn);
    float h = g_scratch[OFF_VEC1 + H + j];
    float hn = (1.f - z) * n + z * h;
    g_scratch[OFF_HNEW + j] = hn;
    out_full[V + j] = hn;   // second output: h_new
}

// ---------------- K9: sum of exp(logit - max), deterministic partials ----------------
#define NB_SUM 240
__global__ void k_sumexp() {
    __shared__ float sm[256];
    float m = ord2f(g_maxbits);
    float s = 0.f;
    for (int i = blockIdx.x * blockDim.x + threadIdx.x; i < V; i += NB_SUM * 256)
        s += expf(g_scratch[OFF_LOGITS + i] - m);
    sm[threadIdx.x] = s;
    __syncthreads();
    for (int st = 128; st > 0; st >>= 1) {
        if (threadIdx.x < st) sm[threadIdx.x] += sm[threadIdx.x + st];
        __syncthreads();
    }
    if (threadIdx.x == 0) g_scratch[OFF_PART + blockIdx.x] = sm[0];
}

// ---------------- K10: final reduce (parallel, deterministic) + write ----------------
__global__ void k_write_out(float* __restrict__ out_full) {
    __shared__ float sp[256];
    int t = threadIdx.x;
    sp[t] = (t < NB_SUM) ? g_scratch[OFF_PART + t] : 0.f;
    __syncthreads();
    for (int st = 128; st > 0; st >>= 1) {
        if (t < st) sp[t] += sp[t + st];
        __syncthreads();
    }
    float lse = ord2f(g_maxbits) + logf(sp[0]);
    for (int i = blockIdx.x * blockDim.x + threadIdx.x; i < V; i += gridDim.x * blockDim.x)
        out_full[i] = g_scratch[OFF_LOGITS + i] - lse;
}

// ---------------- launch ----------------
extern "C" void kernel_launch(void* const* d_in, const int* in_sizes, int n_in,
                              void* d_out, int out_size) {
    const int*   input_idx = (const int*)  d_in[0];
    const float* hidden    = (const float*)d_in[1];
    const float* enc       = (const float*)d_in[2];
    const float* emb       = (const float*)d_in[3];
    const float* attn_W    = (const float*)d_in[4];
    const float* attn_b    = (const float*)d_in[5];
    const float* comb_W    = (const float*)d_in[6];
    const float* comb_b    = (const float*)d_in[7];
    const float* W_ih      = (const float*)d_in[8];
    const float* W_hh      = (const float*)d_in[9];
    const float* b_ih      = (const float*)d_in[10];
    const float* b_hh      = (const float*)d_in[11];
    const float* out_W     = (const float*)d_in[12];
    const float* out_b     = (const float*)d_in[13];
    float* out = (float*)d_out;

    // K1: gather embedding + hidden into scratch
    k_init<<<8, 256>>>(input_idx, hidden, emb);
    // K2: attention logits = cat(emb,h) @ attn_W.T + attn_b
    k_matvec<<<64, 256, 2 * H * sizeof(float)>>>(attn_W, attn_b, OFF_VEC1,
                                                 OFF_ALOG, L, 2 * H, 0);
    // K3: softmax(512), writes attn_weights output
    k_attn_softmax<<<1, 512>>>(out);
    // K4: attn_applied = aw @ encoder_output
    k_attn_apply_part<<<dim3(4, 8), 256>>>(enc);
    k_attn_apply_reduce<<<4, 256>>>();
    // K5: x = relu(cat(emb, attn_applied) @ comb_W.T + comb_b)
    k_matvec<<<128, 256, 2 * H * sizeof(float)>>>(comb_W, comb_b, OFF_VEC2,
                                                  OFF_X, H, 2 * H, 1);
    // K5b: gh = h @ W_hh.T + b_hh  (depends only on h)
    k_matvec<<<384, 256, H * sizeof(float)>>>(W_hh, b_hh, OFF_VEC1 + H,
                                              OFF_GH, 3 * H, H, 0);
    // K6: gi = x @ W_ih.T + b_ih
    k_matvec<<<384, 256, H * sizeof(float)>>>(W_ih, b_ih, OFF_X,
                                              OFF_GI, 3 * H, H, 0);
    // K7: GRU gates -> h_new (writes h_new output)
    k_gates<<<4, 256>>>(out);
    // K8: vocab logits = h_new @ out_W.T + out_b, with running max
    k_matvec<<<(V + 7) / 8, 256, H * sizeof(float)>>>(out_W, out_b, OFF_HNEW,
                                                      OFF_LOGITS, V, H, 2);
    // K9/K10: deterministic log-softmax
    k_sumexp<<<NB_SUM, 256>>>();
    k_write_out<<<240, 256>>>(out);
}

// round 4
// speedup vs baseline: 1.2080x; 1.2080x over previous
#include <cuda_runtime.h>
#include <math.h>

#define H 1024
#define L 512
#define V 50257

// ---------------- scratch layout (floats) ----------------
#define OFF_ALOG   0        // attn logits (512)
#define OFF_ATT    512      // attn_applied accumulator (1024)
#define OFF_X      1536     // GRU input x (1024)
#define OFF_GI     2560     // gi (3072)
#define OFF_GH     5632     // gh (3072)
#define OFF_HNEW   8704     // h_new (1024)
#define OFF_LOGITS 9728     // vocab logits (50257)
#define OFF_PART   59985    // 240 partial exp-sums
#define OFF_LSE    60225
#define SCRATCH_FLOATS 60240

__device__ float g_scratch[SCRATCH_FLOATS];
__device__ int   g_maxbits;  // ordered-int running max of vocab logits
__device__ int   g_count;    // arrival counter for fused log-softmax
__device__ int   g_flag;     // lse-ready flag

__device__ __forceinline__ int f2ord(float f) {
    int i = __float_as_int(f);
    return (i >= 0) ? i : (i ^ 0x7FFFFFFF);
}
__device__ __forceinline__ float ord2f(int o) {
    return __int_as_float((o >= 0) ? o : (o ^ 0x7FFFFFFF));
}

// ---------------- N1: attn logits = cat(emb[idx], h) @ attn_W.T + b ----------------
// Also: block 0 zeroes the attn_applied accumulator and resets control words.
__global__ void __launch_bounds__(256)
k_attn(const float* __restrict__ attn_W, const float* __restrict__ attn_b,
       const int* __restrict__ idx, const float* __restrict__ hidden,
       const float* __restrict__ emb) {
    __shared__ float sv[2 * H];
    int t = threadIdx.x;
    int row_e = idx[0];
    // gather: first half emb row, second half hidden
    #pragma unroll
    for (int i = t; i < H; i += 256) {
        sv[i]     = emb[(size_t)row_e * H + i];
        sv[H + i] = hidden[i];
    }
    if (blockIdx.x == 0) {
        for (int i = t; i < H; i += 256) g_scratch[OFF_ATT + i] = 0.f;
        if (t == 0) { g_maxbits = 0x80000000; g_count = 0; g_flag = 0; }
    }
    __syncthreads();

    int warp = t >> 5, lane = t & 31;
    int row = blockIdx.x * 8 + warp;               // L=512, grid 64
    const float4* wr = (const float4*)(attn_W + (size_t)row * 2 * H);
    const float4* v4 = (const float4*)sv;
    float acc = 0.f;
    #pragma unroll
    for (int i = lane; i < 512; i += 32) {
        float4 w = wr[i]; float4 x = v4[i];
        acc += w.x * x.x + w.y * x.y + w.z * x.z + w.w * x.w;
    }
    #pragma unroll
    for (int o = 16; o; o >>= 1) acc += __shfl_xor_sync(0xFFFFFFFFu, acc, o);
    if (lane == 0) g_scratch[OFF_ALOG + row] = acc + attn_b[row];
}

// ---------------- N2: per-block softmax(512) + attn_applied partial ----------------
// grid (4 col-groups x 16 L-chunks), 256 threads. Block (0,0) writes aw output.
__global__ void __launch_bounds__(256)
k_apply(const float* __restrict__ enc, float* __restrict__ out_full) {
    __shared__ float aw[512];
    __shared__ float sred[256];
    int t = threadIdx.x;
    float v0 = g_scratch[OFF_ALOG + t];
    float v1 = g_scratch[OFF_ALOG + 256 + t];
    sred[t] = fmaxf(v0, v1);
    __syncthreads();
    #pragma unroll
    for (int s = 128; s > 0; s >>= 1) {
        if (t < s) sred[t] = fmaxf(sred[t], sred[t + s]);
        __syncthreads();
    }
    float mx = sred[0];
    __syncthreads();
    float e0 = expf(v0 - mx), e1 = expf(v1 - mx);
    sred[t] = e0 + e1;
    __syncthreads();
    #pragma unroll
    for (int s = 128; s > 0; s >>= 1) {
        if (t < s) sred[t] += sred[t + s];
        __syncthreads();
    }
    float inv = 1.f / sred[0];
    aw[t] = e0 * inv; aw[256 + t] = e1 * inv;
    __syncthreads();
    if (blockIdx.x == 0 && blockIdx.y == 0) {
        out_full[V + H + t]       = aw[t];
        out_full[V + H + 256 + t] = aw[256 + t];
    }
    int col  = blockIdx.x * 256 + t;
    int base = blockIdx.y * 32;
    float s = 0.f;
    #pragma unroll
    for (int l = 0; l < 32; l++)
        s += aw[base + l] * enc[(size_t)(base + l) * H + col];
    atomicAdd(&g_scratch[OFF_ATT + col], s);
}

// ---------------- N3: x = relu(cat(emb[idx], attn_applied) @ comb_W.T + b) ----------------
__global__ void __launch_bounds__(256)
k_comb(const float* __restrict__ comb_W, const float* __restrict__ comb_b,
       const int* __restrict__ idx, const float* __restrict__ emb) {
    __shared__ float sv[2 * H];
    int t = threadIdx.x;
    int row_e = idx[0];
    #pragma unroll
    for (int i = t; i < H; i += 256) {
        sv[i]     = emb[(size_t)row_e * H + i];
        sv[H + i] = g_scratch[OFF_ATT + i];
    }
    __syncthreads();
    int warp = t >> 5, lane = t & 31;
    int row = blockIdx.x * 8 + warp;               // H=1024, grid 128
    const float4* wr = (const float4*)(comb_W + (size_t)row * 2 * H);
    const float4* v4 = (const float4*)sv;
    float acc = 0.f;
    #pragma unroll
    for (int i = lane; i < 512; i += 32) {
        float4 w = wr[i]; float4 x = v4[i];
        acc += w.x * x.x + w.y * x.y + w.z * x.z + w.w * x.w;
    }
    #pragma unroll
    for (int o = 16; o; o >>= 1) acc += __shfl_xor_sync(0xFFFFFFFFu, acc, o);
    if (lane == 0) g_scratch[OFF_X + row] = fmaxf(acc + comb_b[row], 0.f);
}

// ---------------- N4: gi = x@W_ih.T+b_ih  and  gh = h@W_hh.T+b_hh (merged, 6144 rows) ----------------
__global__ void __launch_bounds__(256)
k_gih(const float* __restrict__ W_ih, const float* __restrict__ b_ih,
      const float* __restrict__ W_hh, const float* __restrict__ b_hh,
      const float* __restrict__ hidden) {
    __shared__ float sx[H], sh[H];
    int t = threadIdx.x;
    #pragma unroll
    for (int i = t; i < H; i += 256) {
        sx[i] = g_scratch[OFF_X + i];
        sh[i] = hidden[i];
    }
    __syncthreads();
    int warp = t >> 5, lane = t & 31;
    int row = blockIdx.x * 8 + warp;               // 0..6143, grid 768
    const float* W; const float* b; const float* vv; int r; int outoff;
    if (row < 3 * H) { W = W_ih; b = b_ih; vv = sx; r = row;          outoff = OFF_GI; }
    else             { W = W_hh; b = b_hh; vv = sh; r = row - 3 * H;  outoff = OFF_GH; }
    const float4* wr = (const float4*)(W + (size_t)r * H);
    const float4* v4 = (const float4*)vv;
    float acc = 0.f;
    #pragma unroll
    for (int i = lane; i < 256; i += 32) {
        float4 w = wr[i]; float4 x = v4[i];
        acc += w.x * x.x + w.y * x.y + w.z * x.z + w.w * x.w;
    }
    #pragma unroll
    for (int o = 16; o; o >>= 1) acc += __shfl_xor_sync(0xFFFFFFFFu, acc, o);
    if (lane == 0) g_scratch[outoff + r] = acc + b[r];
}

// ---------------- N5: GRU gates -> h_new ----------------
__global__ void k_gates(const float* __restrict__ hidden, float* __restrict__ out_full) {
    int j = blockIdx.x * blockDim.x + threadIdx.x;   // 0..1023
    float gir = g_scratch[OFF_GI + j],       ghr = g_scratch[OFF_GH + j];
    float giz = g_scratch[OFF_GI + H + j],   ghz = g_scratch[OFF_GH + H + j];
    float gin = g_scratch[OFF_GI + 2*H + j], ghn = g_scratch[OFF_GH + 2*H + j];
    float r = 1.f / (1.f + expf(-(gir + ghr)));
    float z = 1.f / (1.f + expf(-(giz + ghz)));
    float n = tanhf(gin + r * ghn);
    float hn = (1.f - z) * n + z * hidden[j];
    g_scratch[OFF_HNEW + j] = hn;
    out_full[V + j] = hn;                            // second output
}

// ---------------- N6: vocab logits = h_new @ out_W.T + out_b, block-level max ----------------
__global__ void __launch_bounds__(256)
k_vocab(const float* __restrict__ out_W, const float* __restrict__ out_b) {
    __shared__ float sv[H];
    __shared__ float srow[8];
    int t = threadIdx.x;
    #pragma unroll
    for (int i = t; i < H; i += 256) sv[i] = g_scratch[OFF_HNEW + i];
    __syncthreads();
    int warp = t >> 5, lane = t & 31;
    int row = blockIdx.x * 8 + warp;
    float r = -INFINITY;
    if (row < V) {
        const float4* wr = (const float4*)(out_W + (size_t)row * H);
        const float4* v4 = (const float4*)sv;
        float acc = 0.f;
        #pragma unroll
        for (int i = lane; i < 256; i += 32) {
            float4 w = wr[i]; float4 x = v4[i];
            acc += w.x * x.x + w.y * x.y + w.z * x.z + w.w * x.w;
        }
        #pragma unroll
        for (int o = 16; o; o >>= 1) acc += __shfl_xor_sync(0xFFFFFFFFu, acc, o);
        if (lane == 0) {
            r = acc + out_b[row];
            g_scratch[OFF_LOGITS + row] = r;
        }
    }
    if (lane == 0) srow[warp] = r;
    __syncthreads();
    if (t == 0) {
        float m = srow[0];
        #pragma unroll
        for (int w = 1; w < 8; w++) m = fmaxf(m, srow[w]);
        atomicMax(&g_maxbits, f2ord(m));
    }
}

// ---------------- N7: fused log-softmax (partial sums + last-block lse + spin + write) ----------------
#define NB_SUM 240
__global__ void __launch_bounds__(256)
k_logsoftmax(float* __restrict__ out_full) {
    __shared__ float sm[256];
    int t = threadIdx.x;
    float m = ord2f(g_maxbits);
    float s = 0.f;
    for (int i = blockIdx.x * 256 + t; i < V; i += NB_SUM * 256)
        s += expf(g_scratch[OFF_LOGITS + i] - m);
    sm[t] = s;
    __syncthreads();
    #pragma unroll
    for (int st = 128; st > 0; st >>= 1) {
        if (t < st) sm[t] += sm[t + st];
        __syncthreads();
    }
    if (t == 0) {
        g_scratch[OFF_PART + blockIdx.x] = sm[0];
        __threadfence();
        int old = atomicAdd(&g_count, 1);
        if (old == NB_SUM - 1) {                 // last block: deterministic final reduce
            float tot = 0.f;
            #pragma unroll 8
            for (int p = 0; p < NB_SUM; p++) tot += g_scratch[OFF_PART + p];
            g_scratch[OFF_LSE] = m + logf(tot);
            __threadfence();
            atomicExch(&g_flag, 1);
        }
        while (atomicAdd(&g_flag, 0) == 0) { }   // all 240 blocks resident (2/SM)
    }
    __syncthreads();
    float lse = g_scratch[OFF_LSE];
    for (int i = blockIdx.x * 256 + t; i < V; i += NB_SUM * 256)
        out_full[i] = g_scratch[OFF_LOGITS + i] - lse;
}

// ---------------- launch: 7 graph nodes ----------------
extern "C" void kernel_launch(void* const* d_in, const int* in_sizes, int n_in,
                              void* d_out, int out_size) {
    const int*   input_idx = (const int*)  d_in[0];
    const float* hidden    = (const float*)d_in[1];
    const float* enc       = (const float*)d_in[2];
    const float* emb       = (const float*)d_in[3];
    const float* attn_W    = (const float*)d_in[4];
    const float* attn_b    = (const float*)d_in[5];
    const float* comb_W    = (const float*)d_in[6];
    const float* comb_b    = (const float*)d_in[7];
    const float* W_ih      = (const float*)d_in[8];
    const float* W_hh      = (const float*)d_in[9];
    const float* b_ih      = (const float*)d_in[10];
    const float* b_hh      = (const float*)d_in[11];
    const float* out_W     = (const float*)d_in[12];
    const float* out_b     = (const float*)d_in[13];
    float* out = (float*)d_out;

    k_attn <<<64, 256>>>(attn_W, attn_b, input_idx, hidden, emb);
    k_apply<<<dim3(4, 16), 256>>>(enc, out);
    k_comb <<<128, 256>>>(comb_W, comb_b, input_idx, emb);
    k_gih  <<<768, 256>>>(W_ih, b_ih, W_hh, b_hh, hidden);
    k_gates<<<4, 256>>>(hidden, out);
    k_vocab<<<(V + 7) / 8, 256>>>(out_W, out_b);
    k_logsoftmax<<<NB_SUM, 256>>>(out);
}

// round 6
// speedup vs baseline: 1.2429x; 1.0289x over previous
#include <cuda_runtime.h>
#include <math.h>

#define H 1024
#define L 512
#define V 50257

// ---------------- scratch layout (floats) ----------------
#define OFF_ALOG   0        // attn logits (512)
#define OFF_ATT    512      // attn_applied accumulator (1024)
#define OFF_X      1536     // GRU input x (1024)
#define OFF_GI     2560     // gi (3072)
#define OFF_GH     5632     // gh (3072)
#define OFF_HNEW   8704     // h_new (1024)
#define OFF_LOGITS 9728     // vocab logits (50257)
#define OFF_PART   59985    // 240 partial exp-sums
#define OFF_LSE    60225
#define SCRATCH_FLOATS 60240

__device__ float g_scratch[SCRATCH_FLOATS];
__device__ int   g_maxbits;   // ordered-int running max of vocab logits
__device__ int   g_count_ls;  // arrival counter: log-softmax
__device__ int   g_flag_ls;   // lse-ready flag
__device__ int   g_count_gi;  // arrival counter: gi

__device__ __forceinline__ int f2ord(float f) {
    int i = __float_as_int(f);
    return (i >= 0) ? i : (i ^ 0x7FFFFFFF);
}
__device__ __forceinline__ float ord2f(int o) {
    return __int_as_float((o >= 0) ? o : (o ^ 0x7FFFFFFF));
}

// dot of 8 prefetched float4 against smem vector slice (front-batched loads -> MLP=8)
__device__ __forceinline__ float dot8(const float4* __restrict__ wr,
                                      const float4* __restrict__ v4,
                                      int lane) {
    float4 w0 = __ldcs(wr + lane);
    float4 w1 = __ldcs(wr + lane + 32);
    float4 w2 = __ldcs(wr + lane + 64);
    float4 w3 = __ldcs(wr + lane + 96);
    float4 w4 = __ldcs(wr + lane + 128);
    float4 w5 = __ldcs(wr + lane + 160);
    float4 w6 = __ldcs(wr + lane + 192);
    float4 w7 = __ldcs(wr + lane + 224);
    float4 x0 = v4[lane],       x1 = v4[lane + 32];
    float4 x2 = v4[lane + 64],  x3 = v4[lane + 96];
    float4 x4 = v4[lane + 128], x5 = v4[lane + 160];
    float4 x6 = v4[lane + 192], x7 = v4[lane + 224];
    float a = 0.f;
    a += w0.x*x0.x + w0.y*x0.y + w0.z*x0.z + w0.w*x0.w;
    a += w1.x*x1.x + w1.y*x1.y + w1.z*x1.z + w1.w*x1.w;
    a += w2.x*x2.x + w2.y*x2.y + w2.z*x2.z + w2.w*x2.w;
    a += w3.x*x3.x + w3.y*x3.y + w3.z*x3.z + w3.w*x3.w;
    a += w4.x*x4.x + w4.y*x4.y + w4.z*x4.z + w4.w*x4.w;
    a += w5.x*x5.x + w5.y*x5.y + w5.z*x5.z + w5.w*x5.w;
    a += w6.x*x6.x + w6.y*x6.y + w6.z*x6.z + w6.w*x6.w;
    a += w7.x*x7.x + w7.y*x7.y + w7.z*x7.z + w7.w*x7.w;
    return a;
}

__device__ __forceinline__ float warp_sum(float a) {
    #pragma unroll
    for (int o = 16; o; o >>= 1) a += __shfl_xor_sync(0xFFFFFFFFu, a, o);
    return a;
}

// ---------------- N1: attn logits (blocks 0-63) + gh GEMV (blocks 64-447) ----------------
__global__ void __launch_bounds__(256)
k_attn_gh(const float* __restrict__ attn_W, const float* __restrict__ attn_b,
          const float* __restrict__ W_hh, const float* __restrict__ b_hh,
          const int* __restrict__ idx, const float* __restrict__ hidden,
          const float* __restrict__ emb) {
    __shared__ float sv[2 * H];
    int t = threadIdx.x, bid = blockIdx.x;
    if (bid < 64) {
        int row_e = idx[0];
        #pragma unroll
        for (int i = t; i < H; i += 256) {
            sv[i]     = emb[(size_t)row_e * H + i];
            sv[H + i] = hidden[i];
        }
    } else {
        #pragma unroll
        for (int i = t; i < H; i += 256) sv[i] = hidden[i];
    }
    if (bid == 0) {
        for (int i = t; i < H; i += 256) g_scratch[OFF_ATT + i] = 0.f;
        if (t == 0) { g_maxbits = 0x80000000; g_count_ls = 0; g_flag_ls = 0; g_count_gi = 0; }
    }
    __syncthreads();

    int warp = t >> 5, lane = t & 31;
    const float4* v4 = (const float4*)sv;
    if (bid < 64) {
        int row = bid * 8 + warp;                         // 0..511
        const float4* wr = (const float4*)(attn_W + (size_t)row * 2 * H);
        float acc = dot8(wr, v4, lane) + dot8(wr + 256, v4 + 256, lane);
        acc = warp_sum(acc);
        if (lane == 0) g_scratch[OFF_ALOG + row] = acc + attn_b[row];
    } else {
        int row = (bid - 64) * 8 + warp;                  // 0..3071
        const float4* wr = (const float4*)(W_hh + (size_t)row * H);
        float acc = warp_sum(dot8(wr, v4, lane));
        if (lane == 0) g_scratch[OFF_GH + row] = acc + b_hh[row];
    }
}

// ---------------- N2: per-block softmax(512) + attn_applied partials ----------------
__global__ void __launch_bounds__(256)
k_apply(const float* __restrict__ enc, float* __restrict__ out_full) {
    __shared__ float aw[512];
    __shared__ float sred[256];
    int t = threadIdx.x;
    float v0 = g_scratch[OFF_ALOG + t];
    float v1 = g_scratch[OFF_ALOG + 256 + t];
    sred[t] = fmaxf(v0, v1);
    __syncthreads();
    #pragma unroll
    for (int s = 128; s > 0; s >>= 1) {
        if (t < s) sred[t] = fmaxf(sred[t], sred[t + s]);
        __syncthreads();
    }
    float mx = sred[0];
    __syncthreads();
    float e0 = expf(v0 - mx), e1 = expf(v1 - mx);
    sred[t] = e0 + e1;
    __syncthreads();
    #pragma unroll
    for (int s = 128; s > 0; s >>= 1) {
        if (t < s) sred[t] += sred[t + s];
        __syncthreads();
    }
    float inv = 1.f / sred[0];
    aw[t] = e0 * inv; aw[256 + t] = e1 * inv;
    __syncthreads();
    if (blockIdx.x == 0 && blockIdx.y == 0) {
        out_full[V + H + t]       = aw[t];
        out_full[V + H + 256 + t] = aw[256 + t];
    }
    int col  = blockIdx.x * 256 + t;
    int base = blockIdx.y * 32;
    float s = 0.f;
    #pragma unroll
    for (int l = 0; l < 32; l++)
        s += aw[base + l] * __ldcs(enc + (size_t)(base + l) * H + col);
    atomicAdd(&g_scratch[OFF_ATT + col], s);
}

// ---------------- N3: x = relu(cat(emb[idx], attn_applied) @ comb_W.T + b) ----------------
__global__ void __launch_bounds__(256)
k_comb(const float* __restrict__ comb_W, const float* __restrict__ comb_b,
       const int* __restrict__ idx, const float* __restrict__ emb) {
    __shared__ float sv[2 * H];
    int t = threadIdx.x;
    int row_e = idx[0];
    #pragma unroll
    for (int i = t; i < H; i += 256) {
        sv[i]     = emb[(size_t)row_e * H + i];
        sv[H + i] = g_scratch[OFF_ATT + i];
    }
    __syncthreads();
    int warp = t >> 5, lane = t & 31;
    int row = blockIdx.x * 8 + warp;                      // 0..1023
    const float4* v4 = (const float4*)sv;
    const float4* wr = (const float4*)(comb_W + (size_t)row * 2 * H);
    float acc = dot8(wr, v4, lane) + dot8(wr + 256, v4 + 256, lane);
    acc = warp_sum(acc);
    if (lane == 0) g_scratch[OFF_X + row] = fmaxf(acc + comb_b[row], 0.f);
}

// ---------------- N4: gi GEMV + fused GRU gates (blocks 0-3 after spin) ----------------
// Deadlock-free: 384 blocks x 256 thr all resident in one wave on 148 SMs.
__global__ void __launch_bounds__(256)
k_gi_gates(const float* __restrict__ W_ih, const float* __restrict__ b_ih,
           const float* __restrict__ hidden, float* __restrict__ out_full) {
    __shared__ float sx[H];
    int t = threadIdx.x;
    #pragma unroll
    for (int i = t; i < H; i += 256) sx[i] = g_scratch[OFF_X + i];
    __syncthreads();
    int warp = t >> 5, lane = t & 31;
    int row = blockIdx.x * 8 + warp;                      // 0..3071
    const float4* wr = (const float4*)(W_ih + (size_t)row * H);
    float acc = warp_sum(dot8(wr, (const float4*)sx, lane));
    if (lane == 0) {
        g_scratch[OFF_GI + row] = acc + b_ih[row];
        __threadfence();
    }
    __syncthreads();
    if (t == 0) atomicAdd(&g_count_gi, 1);
    if (blockIdx.x < 4) {                                 // gates: 4 blocks x 256 = 1024
        if (t == 0) {
            while (atomicAdd(&g_count_gi, 0) < 384) { }
            __threadfence();
        }
        __syncthreads();
        int j = blockIdx.x * 256 + t;
        float gir = g_scratch[OFF_GI + j],       ghr = g_scratch[OFF_GH + j];
        float giz = g_scratch[OFF_GI + H + j],   ghz = g_scratch[OFF_GH + H + j];
        float gin = g_scratch[OFF_GI + 2*H + j], ghn = g_scratch[OFF_GH + 2*H + j];
        float r = 1.f / (1.f + expf(-(gir + ghr)));
        float z = 1.f / (1.f + expf(-(giz + ghz)));
        float n = tanhf(gin + r * ghn);
        float hn = (1.f - z) * n + z * hidden[j];
        g_scratch[OFF_HNEW + j] = hn;
        out_full[V + j] = hn;                             // second output
    }
}

// ---------------- N5: vocab logits = h_new @ out_W.T + out_b, block-level max ----------------
__global__ void __launch_bounds__(256)
k_vocab(const float* __restrict__ out_W, const float* __restrict__ out_b) {
    __shared__ float sv[H];
    __shared__ float srow[8];
    int t = threadIdx.x;
    #pragma unroll
    for (int i = t; i < H; i += 256) sv[i] = g_scratch[OFF_HNEW + i];
    __syncthreads();
    int warp = t >> 5, lane = t & 31;
    int row = blockIdx.x * 8 + warp;
    float r = -INFINITY;
    if (row < V) {
        const float4* wr = (const float4*)(out_W + (size_t)row * H);
        float acc = warp_sum(dot8(wr, (const float4*)sv, lane));
        if (lane == 0) {
            r = acc + out_b[row];
            g_scratch[OFF_LOGITS + row] = r;
        }
    }
    if (lane == 0) srow[warp] = r;
    __syncthreads();
    if (t == 0) {
        float m = srow[0];
        #pragma unroll
        for (int w = 1; w < 8; w++) m = fmaxf(m, srow[w]);
        atomicMax(&g_maxbits, f2ord(m));
    }
}

// ---------------- N6: fused log-softmax ----------------
// Deadlock-free: 240 blocks x 256 thr, one wave.
#define NB_SUM 240
__global__ void __launch_bounds__(256)
k_logsoftmax(float* __restrict__ out_full) {
    __shared__ float sm[256];
    int t = threadIdx.x;
    float m = ord2f(g_maxbits);
    float s = 0.f;
    for (int i = blockIdx.x * 256 + t; i < V; i += NB_SUM * 256)
        s += expf(g_scratch[OFF_LOGITS + i] - m);
    sm[t] = s;
    __syncthreads();
    #pragma unroll
    for (int st = 128; st > 0; st >>= 1) {
        if (t < st) sm[t] += sm[t + st];
        __syncthreads();
    }
    if (t == 0) {
        g_scratch[OFF_PART + blockIdx.x] = sm[0];
        __threadfence();
        int old = atomicAdd(&g_count_ls, 1);
        if (old == NB_SUM - 1) {
            float tot = 0.f;
            #pragma unroll 8
            for (int p = 0; p < NB_SUM; p++) tot += g_scratch[OFF_PART + p];
            g_scratch[OFF_LSE] = m + logf(tot);
            __threadfence();
            atomicExch(&g_flag_ls, 1);
        }
        while (atomicAdd(&g_flag_ls, 0) == 0) { }
        __threadfence();
    }
    __syncthreads();
    float lse = g_scratch[OFF_LSE];
    for (int i = blockIdx.x * 256 + t; i < V; i += NB_SUM * 256)
        out_full[i] = g_scratch[OFF_LOGITS + i] - lse;
}

// ---------------- launch: 6 graph nodes ----------------
extern "C" void kernel_launch(void* const* d_in, const int* in_sizes, int n_in,
                              void* d_out, int out_size) {
    const int*   input_idx = (const int*)  d_in[0];
    const float* hidden    = (const float*)d_in[1];
    const float* enc       = (const float*)d_in[2];
    const float* emb       = (const float*)d_in[3];
    const float* attn_W    = (const float*)d_in[4];
    const float* attn_b    = (const float*)d_in[5];
    const float* comb_W    = (const float*)d_in[6];
    const float* comb_b    = (const float*)d_in[7];
    const float* W_ih      = (const float*)d_in[8];
    const float* W_hh      = (const float*)d_in[9];
    const float* b_ih      = (const float*)d_in[10];
    const float* b_hh      = (const float*)d_in[11];
    const float* out_W     = (const float*)d_in[12];
    const float* out_b     = (const float*)d_in[13];
    float* out = (float*)d_out;

    k_attn_gh   <<<448, 256>>>(attn_W, attn_b, W_hh, b_hh, input_idx, hidden, emb);
    k_apply     <<<dim3(4, 16), 256>>>(enc, out);
    k_comb      <<<128, 256>>>(comb_W, comb_b, input_idx, emb);
    k_gi_gates  <<<384, 256>>>(W_ih, b_ih, hidden, out);
    k_vocab     <<<(V + 7) / 8, 256>>>(out_W, out_b);
    k_logsoftmax<<<NB_SUM, 256>>>(out);
}